// round 1
// baseline (speedup 1.0000x reference)
#include <cuda_runtime.h>

#define DIN 128
#define DH  128
#define MAXN 100000
#define MAXE 1600000

typedef unsigned long long ull;

// ---- scratch (device globals: no allocation allowed) ----
__device__ int   g_deg[MAXN];
__device__ int   g_cursor[MAXN];
__device__ int   g_rowptr[MAXN + 1];
__device__ int   g_csr[MAXE];
__device__ int   g_bsums[128];
__device__ float g_mean[(size_t)MAXN * DH];
__device__ float g_h[(size_t)MAXN * DH];

// ---- packed f32x2 helpers (PTX-only; ptxas never auto-fuses FFMA2) ----
__device__ __forceinline__ ull pack2(float lo, float hi) {
    ull r; asm("mov.b64 %0, {%1, %2};" : "=l"(r) : "f"(lo), "f"(hi)); return r;
}
__device__ __forceinline__ void unpack2(ull v, float& lo, float& hi) {
    asm("mov.b64 {%0, %1}, %2;" : "=f"(lo), "=f"(hi) : "l"(v));
}
__device__ __forceinline__ void fma2(ull& d, ull a, ull b) {
    asm("fma.rn.f32x2 %0, %1, %2, %0;" : "+l"(d) : "l"(a), "l"(b));
}

// ============================ CSR build ============================

__global__ void k_zero(int n) {
    int i = blockIdx.x * blockDim.x + threadIdx.x;
    if (i < n) { g_deg[i] = 0; g_cursor[i] = 0; }
}

__global__ void k_count(const int* __restrict__ col, int e) {
    int i = blockIdx.x * blockDim.x + threadIdx.x;
    if (i < e) atomicAdd(&g_deg[col[i]], 1);
}

// block-level inclusive scan (1024 elems/block), writes partials + block sums
__global__ void k_scan1(int n) {
    __shared__ int sh[1024];
    int i = blockIdx.x * 1024 + threadIdx.x;
    int v = (i < n) ? g_deg[i] : 0;
    sh[threadIdx.x] = v;
    __syncthreads();
    #pragma unroll
    for (int off = 1; off < 1024; off <<= 1) {
        int t = (threadIdx.x >= off) ? sh[threadIdx.x - off] : 0;
        __syncthreads();
        sh[threadIdx.x] += t;
        __syncthreads();
    }
    if (i < n) g_rowptr[i + 1] = sh[threadIdx.x];
    if (threadIdx.x == 1023) g_bsums[blockIdx.x] = sh[1023];
}

// single block: exclusive scan of (<=128) block sums in place
__global__ void k_scan2(int nb) {
    __shared__ int sh[128];
    int v = (threadIdx.x < nb) ? g_bsums[threadIdx.x] : 0;
    sh[threadIdx.x] = v;
    __syncthreads();
    #pragma unroll
    for (int off = 1; off < 128; off <<= 1) {
        int t = (threadIdx.x >= off) ? sh[threadIdx.x - off] : 0;
        __syncthreads();
        sh[threadIdx.x] += t;
        __syncthreads();
    }
    if (threadIdx.x < nb)
        g_bsums[threadIdx.x] = (threadIdx.x == 0) ? 0 : sh[threadIdx.x - 1];
}

__global__ void k_scan3(int n) {
    int i = blockIdx.x * blockDim.x + threadIdx.x;
    if (i == 0) g_rowptr[0] = 0;
    if (i < n) g_rowptr[i + 1] += g_bsums[i >> 10];
}

__global__ void k_scatter(const int* __restrict__ row, const int* __restrict__ col, int e) {
    int i = blockIdx.x * blockDim.x + threadIdx.x;
    if (i < e) {
        int c = col[i];
        int pos = g_rowptr[c] + atomicAdd(&g_cursor[c], 1);
        g_csr[pos] = row[i];
    }
}

// ============================ mean aggregation ============================
// one warp per target node; each lane owns 4 contiguous features (float4)
__global__ void k_agg(const float* __restrict__ feat, float* __restrict__ mean, int n) {
    int w = (blockIdx.x * blockDim.x + threadIdx.x) >> 5;
    int lane = threadIdx.x & 31;
    if (w >= n) return;
    int s = g_rowptr[w], eend = g_rowptr[w + 1];
    float4 acc = make_float4(0.f, 0.f, 0.f, 0.f);
    int i = s;
    // unroll-by-4 for MLP
    for (; i + 4 <= eend; i += 4) {
        int s0 = g_csr[i], s1 = g_csr[i + 1], s2 = g_csr[i + 2], s3 = g_csr[i + 3];
        float4 v0 = *(const float4*)(feat + (size_t)s0 * DIN + lane * 4);
        float4 v1 = *(const float4*)(feat + (size_t)s1 * DIN + lane * 4);
        float4 v2 = *(const float4*)(feat + (size_t)s2 * DIN + lane * 4);
        float4 v3 = *(const float4*)(feat + (size_t)s3 * DIN + lane * 4);
        acc.x += (v0.x + v1.x) + (v2.x + v3.x);
        acc.y += (v0.y + v1.y) + (v2.y + v3.y);
        acc.z += (v0.z + v1.z) + (v2.z + v3.z);
        acc.w += (v0.w + v1.w) + (v2.w + v3.w);
    }
    for (; i < eend; ++i) {
        int s0 = g_csr[i];
        float4 v = *(const float4*)(feat + (size_t)s0 * DIN + lane * 4);
        acc.x += v.x; acc.y += v.y; acc.z += v.z; acc.w += v.w;
    }
    float inv = 1.0f / fmaxf((float)(eend - s), 1.0f);
    acc.x *= inv; acc.y *= inv; acc.z *= inv; acc.w *= inv;
    *(float4*)(mean + (size_t)w * DH + lane * 4) = acc;
}

// ============================ fused linear ============================
// out[m, :] = relu( mean[m,:] @ Wl + bias + xin[m,:] @ Wr )
// GEMM: M = n nodes, N = 128, K = 256 (concat of mean|xin).
// 128x128 block tile, BK=16, 256 threads, 8x8 register tile, packed f32x2 FMA.
__global__ void __launch_bounds__(256) k_linear(
    const float* __restrict__ Am, const float* __restrict__ Ax,
    const float* __restrict__ Wl, const float* __restrict__ Wr,
    const float* __restrict__ bias, float* __restrict__ out, int n)
{
    __shared__ float As[16][132];   // A transposed: As[k][m], padded
    __shared__ float Bs[16][128];
    int bm = blockIdx.x * 128;
    int tid = (int)threadIdx.x;
    int tx = tid & 15, ty = tid >> 4;

    ull acc[8][4];
    #pragma unroll
    for (int i = 0; i < 8; i++)
        #pragma unroll
        for (int j = 0; j < 4; j++) acc[i][j] = 0ull;  // (0.0f, 0.0f)

    int r = tid >> 2, c4 = tid & 3;

    #pragma unroll 1
    for (int kc = 0; kc < 16; ++kc) {
        const float* Ap = (kc < 8) ? Am : Ax;
        const float* Bp = (kc < 8) ? Wl : Wr;
        int kbase = (kc & 7) * 16;

        // load A tile 128x16 (transposed into As)
        #pragma unroll
        for (int rr = 0; rr < 2; rr++) {
            int m = r + rr * 64;
            int gm = bm + m;
            float4 v = make_float4(0.f, 0.f, 0.f, 0.f);
            if (gm < n) v = *(const float4*)(Ap + (size_t)gm * 128 + kbase + c4 * 4);
            As[c4 * 4 + 0][m] = v.x;
            As[c4 * 4 + 1][m] = v.y;
            As[c4 * 4 + 2][m] = v.z;
            As[c4 * 4 + 3][m] = v.w;
        }
        // load B tile 16x128
        #pragma unroll
        for (int ii = 0; ii < 2; ii++) {
            int l = tid + ii * 256;
            int k = l >> 5, n4 = l & 31;
            *(float4*)&Bs[k][n4 * 4] = *(const float4*)(Bp + (size_t)(kbase + k) * 128 + n4 * 4);
        }
        __syncthreads();

        #pragma unroll
        for (int k = 0; k < 16; k++) {
            float4 a0 = *(float4*)&As[k][ty * 8];
            float4 a1 = *(float4*)&As[k][ty * 8 + 4];
            float4 b0 = *(float4*)&Bs[k][tx * 8];
            float4 b1 = *(float4*)&Bs[k][tx * 8 + 4];
            ull bb[4] = { pack2(b0.x, b0.y), pack2(b0.z, b0.w),
                          pack2(b1.x, b1.y), pack2(b1.z, b1.w) };
            float av[8] = { a0.x, a0.y, a0.z, a0.w, a1.x, a1.y, a1.z, a1.w };
            #pragma unroll
            for (int i = 0; i < 8; i++) {
                ull aa = pack2(av[i], av[i]);
                #pragma unroll
                for (int j = 0; j < 4; j++) fma2(acc[i][j], aa, bb[j]);
            }
        }
        __syncthreads();
    }

    // epilogue: bias + relu + store
    float bv[8];
    #pragma unroll
    for (int j = 0; j < 8; j++) bv[j] = bias[tx * 8 + j];
    #pragma unroll
    for (int i = 0; i < 8; i++) {
        int gm = bm + ty * 8 + i;
        if (gm < n) {
            float o[8];
            #pragma unroll
            for (int j = 0; j < 4; j++) {
                float lo, hi;
                unpack2(acc[i][j], lo, hi);
                o[j * 2] = lo; o[j * 2 + 1] = hi;
            }
            #pragma unroll
            for (int j = 0; j < 8; j++) o[j] = fmaxf(o[j] + bv[j], 0.f);
            *(float4*)(out + (size_t)gm * 128 + tx * 8)     = make_float4(o[0], o[1], o[2], o[3]);
            *(float4*)(out + (size_t)gm * 128 + tx * 8 + 4) = make_float4(o[4], o[5], o[6], o[7]);
        }
    }
}

// ============================ launch ============================

extern "C" void kernel_launch(void* const* d_in, const int* in_sizes, int n_in,
                              void* d_out, int out_size) {
    const float* x   = (const float*)d_in[0];
    const int*   ei  = (const int*)d_in[1];
    const float* w1l = (const float*)d_in[2];
    const float* b1l = (const float*)d_in[3];
    const float* w1r = (const float*)d_in[4];
    const float* w2l = (const float*)d_in[5];
    const float* b2l = (const float*)d_in[6];
    const float* w2r = (const float*)d_in[7];
    float* out = (float*)d_out;

    int n = in_sizes[0] / DIN;
    int e = in_sizes[1] / 2;
    if (n > MAXN) n = MAXN;
    if (e > MAXE) e = MAXE;
    const int* row = ei;       // edge_index[0] = source
    const int* col = ei + e;   // edge_index[1] = target

    void* pmean = nullptr; void* ph = nullptr;
    cudaGetSymbolAddress(&pmean, g_mean);
    cudaGetSymbolAddress(&ph, g_h);
    float* dmean = (float*)pmean;
    float* dh    = (float*)ph;

    // CSR build (shared by both layers)
    k_zero   <<<(n + 255) / 256, 256>>>(n);
    k_count  <<<(e + 255) / 256, 256>>>(col, e);
    int nb = (n + 1023) / 1024;
    k_scan1  <<<nb, 1024>>>(n);
    k_scan2  <<<1, 128>>>(nb);
    k_scan3  <<<(n + 255) / 256, 256>>>(n);
    k_scatter<<<(e + 255) / 256, 256>>>(row, col, e);

    // layer 1
    k_agg    <<<(n * 32 + 255) / 256, 256>>>(x, dmean, n);
    k_linear <<<(n + 127) / 128, 256>>>(dmean, x, w1l, w1r, b1l, dh, n);

    // layer 2
    k_agg    <<<(n * 32 + 255) / 256, 256>>>(dh, dmean, n);
    k_linear <<<(n + 127) / 128, 256>>>(dmean, dh, w2l, w2r, b2l, out, n);
}

// round 2
// speedup vs baseline: 2.1568x; 2.1568x over previous
#include <cuda_runtime.h>
#include <cuda_fp16.h>

#define DIN 128
#define DH  128
#define MAXN 100000
#define MAXE 1600000

typedef unsigned long long ull;
typedef unsigned int uint32;

// ---- scratch (device globals: no allocation allowed) ----
__device__ int   g_deg[MAXN];
__device__ int   g_cursor[MAXN];
__device__ int   g_rowptr[MAXN + 1];
__device__ int   g_csr[MAXE];
__device__ int   g_bsums[128];
__device__ unsigned short g_xh[(size_t)MAXN * DIN];    // x in fp16
__device__ unsigned short g_meanh[(size_t)MAXN * DH];  // mean in fp16
__device__ unsigned short g_hh[(size_t)MAXN * DH];     // hidden in fp16
__device__ unsigned short g_W1[256 * 128];             // [w1l; w1r] fp16
__device__ unsigned short g_W2[256 * 128];             // [w2l; w2r] fp16

// ============================ CSR build ============================

__global__ void k_zero(int n) {
    int i = blockIdx.x * blockDim.x + threadIdx.x;
    if (i < n) { g_deg[i] = 0; g_cursor[i] = 0; }
}

__global__ void k_count(const int* __restrict__ col, int e) {
    int i = blockIdx.x * blockDim.x + threadIdx.x;
    if (i < e) atomicAdd(&g_deg[col[i]], 1);
}

__global__ void k_scan1(int n) {
    __shared__ int sh[1024];
    int i = blockIdx.x * 1024 + threadIdx.x;
    int v = (i < n) ? g_deg[i] : 0;
    sh[threadIdx.x] = v;
    __syncthreads();
    #pragma unroll
    for (int off = 1; off < 1024; off <<= 1) {
        int t = (threadIdx.x >= off) ? sh[threadIdx.x - off] : 0;
        __syncthreads();
        sh[threadIdx.x] += t;
        __syncthreads();
    }
    if (i < n) g_rowptr[i + 1] = sh[threadIdx.x];
    if (threadIdx.x == 1023) g_bsums[blockIdx.x] = sh[1023];
}

__global__ void k_scan2(int nb) {
    __shared__ int sh[128];
    int v = (threadIdx.x < nb) ? g_bsums[threadIdx.x] : 0;
    sh[threadIdx.x] = v;
    __syncthreads();
    #pragma unroll
    for (int off = 1; off < 128; off <<= 1) {
        int t = (threadIdx.x >= off) ? sh[threadIdx.x - off] : 0;
        __syncthreads();
        sh[threadIdx.x] += t;
        __syncthreads();
    }
    if (threadIdx.x < nb)
        g_bsums[threadIdx.x] = (threadIdx.x == 0) ? 0 : sh[threadIdx.x - 1];
}

__global__ void k_scan3(int n) {
    int i = blockIdx.x * blockDim.x + threadIdx.x;
    if (i == 0) g_rowptr[0] = 0;
    if (i < n) g_rowptr[i + 1] += g_bsums[i >> 10];
}

__global__ void k_scatter(const int* __restrict__ row, const int* __restrict__ col, int e) {
    int i = blockIdx.x * blockDim.x + threadIdx.x;
    if (i < e) {
        int c = col[i];
        int pos = g_rowptr[c] + atomicAdd(&g_cursor[c], 1);
        g_csr[pos] = row[i];
    }
}

// ============================ conversions ============================

__global__ void k_cvt(const float* __restrict__ x, __half* __restrict__ xh, int total4) {
    int i = blockIdx.x * blockDim.x + threadIdx.x;
    if (i < total4) {
        float4 v = *(const float4*)(x + (size_t)i * 4);
        __half2 h0 = __floats2half2_rn(v.x, v.y);
        __half2 h1 = __floats2half2_rn(v.z, v.w);
        uint2 o; o.x = *(uint32*)&h0; o.y = *(uint32*)&h1;
        *(uint2*)(xh + (size_t)i * 4) = o;
    }
}

__global__ void k_wcvt(const float* __restrict__ w1l, const float* __restrict__ w1r,
                       const float* __restrict__ w2l, const float* __restrict__ w2r,
                       __half* __restrict__ W1, __half* __restrict__ W2) {
    int i = blockIdx.x * blockDim.x + threadIdx.x;   // 0..16383
    if (i < 128 * 128) {
        W1[i]             = __float2half_rn(w1l[i]);
        W1[128 * 128 + i] = __float2half_rn(w1r[i]);
        W2[i]             = __float2half_rn(w2l[i]);
        W2[128 * 128 + i] = __float2half_rn(w2r[i]);
    }
}

// ============================ mean aggregation (fp16 gather) ============================
// one warp per target node; each lane owns 4 contiguous fp16 features (8B)
__global__ void k_agg_h(const __half* __restrict__ feat, __half* __restrict__ mean, int n) {
    int w = (blockIdx.x * blockDim.x + threadIdx.x) >> 5;
    int lane = threadIdx.x & 31;
    if (w >= n) return;
    int s = g_rowptr[w], eend = g_rowptr[w + 1];
    float2 a0 = make_float2(0.f, 0.f), a1 = make_float2(0.f, 0.f);
    int i = s;
    for (; i + 4 <= eend; i += 4) {
        int s0 = g_csr[i], s1 = g_csr[i + 1], s2 = g_csr[i + 2], s3 = g_csr[i + 3];
        uint2 v0 = *(const uint2*)(feat + (size_t)s0 * DIN + lane * 4);
        uint2 v1 = *(const uint2*)(feat + (size_t)s1 * DIN + lane * 4);
        uint2 v2 = *(const uint2*)(feat + (size_t)s2 * DIN + lane * 4);
        uint2 v3 = *(const uint2*)(feat + (size_t)s3 * DIN + lane * 4);
        float2 f;
        f = __half22float2(*(__half2*)&v0.x); a0.x += f.x; a0.y += f.y;
        f = __half22float2(*(__half2*)&v0.y); a1.x += f.x; a1.y += f.y;
        f = __half22float2(*(__half2*)&v1.x); a0.x += f.x; a0.y += f.y;
        f = __half22float2(*(__half2*)&v1.y); a1.x += f.x; a1.y += f.y;
        f = __half22float2(*(__half2*)&v2.x); a0.x += f.x; a0.y += f.y;
        f = __half22float2(*(__half2*)&v2.y); a1.x += f.x; a1.y += f.y;
        f = __half22float2(*(__half2*)&v3.x); a0.x += f.x; a0.y += f.y;
        f = __half22float2(*(__half2*)&v3.y); a1.x += f.x; a1.y += f.y;
    }
    for (; i < eend; ++i) {
        int s0 = g_csr[i];
        uint2 v = *(const uint2*)(feat + (size_t)s0 * DIN + lane * 4);
        float2 f;
        f = __half22float2(*(__half2*)&v.x); a0.x += f.x; a0.y += f.y;
        f = __half22float2(*(__half2*)&v.y); a1.x += f.x; a1.y += f.y;
    }
    float inv = 1.0f / fmaxf((float)(eend - s), 1.0f);
    __half2 h0 = __floats2half2_rn(a0.x * inv, a0.y * inv);
    __half2 h1 = __floats2half2_rn(a1.x * inv, a1.y * inv);
    uint2 o; o.x = *(uint32*)&h0; o.y = *(uint32*)&h1;
    *(uint2*)(mean + (size_t)w * DH + lane * 4) = o;
}

// ============================ HMMA fused linear ============================
// out[m,:] = relu( [mean|xin] @ [Wl;Wr] + bias ), K=256, N=128.
// Block: 256 threads (8 warps), 128 M-rows. Warp = 16 rows. mma.sync m16n8k16.

__device__ __forceinline__ void ldmx4(uint32& r0, uint32& r1, uint32& r2, uint32& r3, const void* p) {
    uint32 a = (uint32)__cvta_generic_to_shared(p);
    asm volatile("ldmatrix.sync.aligned.m8n8.x4.shared.b16 {%0,%1,%2,%3}, [%4];"
                 : "=r"(r0), "=r"(r1), "=r"(r2), "=r"(r3) : "r"(a));
}
__device__ __forceinline__ void ldmx4t(uint32& r0, uint32& r1, uint32& r2, uint32& r3, const void* p) {
    uint32 a = (uint32)__cvta_generic_to_shared(p);
    asm volatile("ldmatrix.sync.aligned.m8n8.x4.trans.shared.b16 {%0,%1,%2,%3}, [%4];"
                 : "=r"(r0), "=r"(r1), "=r"(r2), "=r"(r3) : "r"(a));
}
__device__ __forceinline__ void mma16816(float* c, uint32 a0, uint32 a1, uint32 a2, uint32 a3,
                                         uint32 b0, uint32 b1) {
    asm volatile("mma.sync.aligned.m16n8k16.row.col.f32.f16.f16.f32 "
                 "{%0,%1,%2,%3}, {%4,%5,%6,%7}, {%8,%9}, {%0,%1,%2,%3};"
                 : "+f"(c[0]), "+f"(c[1]), "+f"(c[2]), "+f"(c[3])
                 : "r"(a0), "r"(a1), "r"(a2), "r"(a3), "r"(b0), "r"(b1));
}

template <int HALF_OUT>
__global__ void __launch_bounds__(256) k_gemm(
    const __half* __restrict__ Am, const __half* __restrict__ Ax,
    const __half* __restrict__ W, const float* __restrict__ bias,
    float* __restrict__ outf, __half* __restrict__ outh, int n)
{
    __shared__ __half As[128][72];   // row stride 144B -> conflict-free ldmatrix
    __shared__ __half Bs[64][136];   // row stride 272B -> conflict-free ldmatrix

    int tid = (int)threadIdx.x;
    int lane = tid & 31;
    int warp = tid >> 5;        // 0..7
    int wm = warp * 16;
    int bm = blockIdx.x * 128;

    float acc[16][4];
    #pragma unroll
    for (int j = 0; j < 16; j++)
        #pragma unroll
        for (int q = 0; q < 4; q++) acc[j][q] = 0.f;

    #pragma unroll 1
    for (int c = 0; c < 4; ++c) {
        // ---- load A chunk 128 x 64 (fp16) ----
        const __half* src = (c < 2) ? Am : Ax;
        int koff = (c & 1) * 64;
        int r = tid >> 1;
        int cbase = (tid & 1) * 32;
        int gr = bm + r;
        #pragma unroll
        for (int j = 0; j < 4; j++) {
            int col = cbase + j * 8;
            uint4 v = make_uint4(0, 0, 0, 0);
            if (gr < n) v = *(const uint4*)(src + (size_t)gr * 128 + koff + col);
            *(uint4*)&As[r][col] = v;
        }
        // ---- load B chunk 64 x 128 (fp16) ----
        #pragma unroll
        for (int j = 0; j < 4; j++) {
            int lin = tid + j * 256;       // 0..1023
            int br = lin >> 4;             // 0..63
            int col = (lin & 15) * 8;
            *(uint4*)&Bs[br][col] = *(const uint4*)(W + (size_t)(c * 64 + br) * 128 + col);
        }
        __syncthreads();

        #pragma unroll
        for (int ks = 0; ks < 4; ks++) {
            uint32 a0, a1, a2, a3;
            ldmx4(a0, a1, a2, a3, &As[wm + (lane & 15)][ks * 16 + (lane >> 4) * 8]);
            #pragma unroll
            for (int nt = 0; nt < 8; nt++) {
                uint32 b0, b1, b2, b3;
                ldmx4t(b0, b1, b2, b3, &Bs[ks * 16 + (lane & 15)][nt * 16 + (lane >> 4) * 8]);
                mma16816(acc[nt * 2],     a0, a1, a2, a3, b0, b1);
                mma16816(acc[nt * 2 + 1], a0, a1, a2, a3, b2, b3);
            }
        }
        __syncthreads();
    }

    // ---- epilogue: bias + relu ----
    int r0 = bm + wm + (lane >> 2);
    int r1 = r0 + 8;
    #pragma unroll
    for (int j = 0; j < 16; j++) {
        int col = j * 8 + (lane & 3) * 2;
        float b0 = bias[col], b1 = bias[col + 1];
        float v00 = fmaxf(acc[j][0] + b0, 0.f);
        float v01 = fmaxf(acc[j][1] + b1, 0.f);
        float v10 = fmaxf(acc[j][2] + b0, 0.f);
        float v11 = fmaxf(acc[j][3] + b1, 0.f);
        if (HALF_OUT) {
            if (r0 < n) { __half2 h = __floats2half2_rn(v00, v01); *(__half2*)(outh + (size_t)r0 * 128 + col) = h; }
            if (r1 < n) { __half2 h = __floats2half2_rn(v10, v11); *(__half2*)(outh + (size_t)r1 * 128 + col) = h; }
        } else {
            if (r0 < n) { *(float2*)(outf + (size_t)r0 * 128 + col) = make_float2(v00, v01); }
            if (r1 < n) { *(float2*)(outf + (size_t)r1 * 128 + col) = make_float2(v10, v11); }
        }
    }
}

// ============================ launch ============================

extern "C" void kernel_launch(void* const* d_in, const int* in_sizes, int n_in,
                              void* d_out, int out_size) {
    const float* x   = (const float*)d_in[0];
    const int*   ei  = (const int*)d_in[1];
    const float* w1l = (const float*)d_in[2];
    const float* b1l = (const float*)d_in[3];
    const float* w1r = (const float*)d_in[4];
    const float* w2l = (const float*)d_in[5];
    const float* b2l = (const float*)d_in[6];
    const float* w2r = (const float*)d_in[7];
    float* out = (float*)d_out;

    int n = in_sizes[0] / DIN;
    int e = in_sizes[1] / 2;
    if (n > MAXN) n = MAXN;
    if (e > MAXE) e = MAXE;
    const int* row = ei;       // edge_index[0] = source
    const int* col = ei + e;   // edge_index[1] = target

    void *pxh, *pmh, *phh, *pw1, *pw2;
    cudaGetSymbolAddress(&pxh, g_xh);
    cudaGetSymbolAddress(&pmh, g_meanh);
    cudaGetSymbolAddress(&phh, g_hh);
    cudaGetSymbolAddress(&pw1, g_W1);
    cudaGetSymbolAddress(&pw2, g_W2);
    __half* xh    = (__half*)pxh;
    __half* meanh = (__half*)pmh;
    __half* hh    = (__half*)phh;
    __half* W1    = (__half*)pw1;
    __half* W2    = (__half*)pw2;

    // CSR build (shared by both layers)
    k_zero   <<<(n + 255) / 256, 256>>>(n);
    k_count  <<<(e + 255) / 256, 256>>>(col, e);
    int nb = (n + 1023) / 1024;
    k_scan1  <<<nb, 1024>>>(n);
    k_scan2  <<<1, 128>>>(nb);
    k_scan3  <<<(n + 255) / 256, 256>>>(n);
    k_scatter<<<(e + 255) / 256, 256>>>(row, col, e);

    // fp16 conversions
    int total4 = (n * DIN) / 4;
    k_cvt  <<<(total4 + 255) / 256, 256>>>(x, xh, total4);
    k_wcvt <<<(128 * 128 + 255) / 256, 256>>>(w1l, w1r, w2l, w2r, W1, W2);

    int aggBlocks = (n * 32 + 255) / 256;
    int gemmBlocks = (n + 127) / 128;

    // layer 1: h = relu([mean(x)|x] @ W1 + b1)  -> fp16 only
    k_agg_h  <<<aggBlocks, 256>>>(xh, meanh, n);
    k_gemm<1><<<gemmBlocks, 256>>>(meanh, xh, W1, b1l, nullptr, hh, n);

    // layer 2: out = relu([mean(h)|h] @ W2 + b2) -> fp32 final
    k_agg_h  <<<aggBlocks, 256>>>(hh, meanh, n);
    k_gemm<0><<<gemmBlocks, 256>>>(meanh, hh, W2, b2l, out, nullptr, n);
}